// round 16
// baseline (speedup 1.0000x reference)
#include <cuda_runtime.h>
#include <math.h>

// RRN sudoku. B=16, N=64, DEG=17, H=96, 32 steps.
// Round 16: CTA = 1 node x 96 threads, grid 1024 (6.9 CTAs/SM, ~21 warps/SM).
// R13 economics scaled down: thread = 3 cols x 3 row-pairs, double-buffered
// weight LDGs, broadcast LDS.64 Z reads.

#define NSTEP 32
#define RS 20            // Z row stride (floats): rows 0..16 real, 17 pad
typedef unsigned long long ull;

// ---------- device scratch (allocation-free) ----------
__device__ float g_P[2][1024 * 96];
__device__ float g_Q[1024 * 96];
__device__ float g_Ghh[1024 * 384];
__device__ float g_Xc[1024 * 384];
__device__ float g_s[1024 * 96];
__device__ float g_nodeloss[NSTEP * 1024];
__device__ int   g_nodeok[NSTEP * 1024];

// ---------- packed f32x2 helpers ----------
__device__ __forceinline__ ull pack2(float x, float y) {
    ull r; asm("mov.b64 %0,{%1,%2};" : "=l"(r) : "f"(x), "f"(y)); return r;
}
__device__ __forceinline__ void unpack2(ull v, float& x, float& y) {
    asm("mov.b64 {%0,%1},%2;" : "=f"(x), "=f"(y) : "l"(v));
}
__device__ __forceinline__ void fma2(ull& d, ull a, ull b) {
    asm("fma.rn.f32x2 %0,%1,%2,%0;" : "+l"(d) : "l"(a), "l"(b));
}
__device__ __forceinline__ float sigf(float x) { return 1.f / (1.f + expf(-x)); }

__device__ __forceinline__ void ldw4(float w[4][3], const float* __restrict__ Wg,
                                     int k, int tx)
{
#pragma unroll
    for (int u = 0; u < 4; u++)
#pragma unroll
        for (int i = 0; i < 3; i++)
            w[u][i] = __ldg(Wg + (k + u) * 96 + tx + 32 * i);
}

__device__ __forceinline__ void blk4(const float* Zin, int k, int rb,
                                     const float w[4][3], ull acc[3][3])
{
#pragma unroll
    for (int u = 0; u < 4; u++) {
        const float* zrow = Zin + (k + u) * RS + rb;
        ull z0 = *(const ull*)(zrow);
        ull z1 = *(const ull*)(zrow + 2);
        ull z2 = *(const ull*)(zrow + 4);
#pragma unroll
        for (int i = 0; i < 3; i++) {
            ull w2 = pack2(w[u][i], w[u][i]);
            fma2(acc[0][i], z0, w2);
            fma2(acc[1][i], z1, w2);
            fma2(acc[2][i], z2, w2);
        }
    }
}

// ---------- 18x96 @ 96x96 k-loop; thread = 3 cols x pairs {3ty..3ty+2} ----------
__device__ __forceinline__ void kloop(const float* Zin,
                                      const float* __restrict__ Wg,
                                      int tx, int ty, ull acc[3][3])
{
#pragma unroll
    for (int j = 0; j < 3; j++)
#pragma unroll
        for (int i = 0; i < 3; i++) acc[j][i] = 0ull;

    const int rb = 6 * ty;
    float wA[4][3], wB[4][3];
    ldw4(wA, Wg, 0, tx);
#pragma unroll 1
    for (int k0 = 0; k0 < 96; k0 += 8) {
        ldw4(wB, Wg, k0 + 4, tx);
        blk4(Zin, k0, rb, wA, acc);
        if (k0 + 8 < 96) ldw4(wA, Wg, k0 + 8, tx);
        blk4(Zin, k0 + 4, rb, wB, acc);
    }
}

// ---------- relu layer ----------
__device__ __forceinline__ void layer_relu(const float* Zin, float* Zout,
                                           const float* __restrict__ Wg,
                                           const float* __restrict__ bias,
                                           int tx, int ty)
{
    ull acc[3][3];
    kloop(Zin, Wg, tx, ty, acc);
#pragma unroll
    for (int i = 0; i < 3; i++) {
        int c = tx + 32 * i;
        float bv = __ldg(bias + c);
#pragma unroll
        for (int j = 0; j < 3; j++) {
            float x, y; unpack2(acc[j][i], x, y);
            *(ull*)(Zout + c * RS + 2 * (3 * ty + j)) =
                pack2(fmaxf(x + bv, 0.f), fmaxf(y + bv, 0.f));
        }
    }
}

// last layer: partial row sums -> spart[ty*96 + c]; ty2 pair 8 drops y (pad row 17)
__device__ __forceinline__ void layer_sum(const float* Zin, float* spart,
                                          const float* __restrict__ Wg,
                                          int tx, int ty)
{
    ull acc[3][3];
    kloop(Zin, Wg, tx, ty, acc);
#pragma unroll
    for (int i = 0; i < 3; i++) {
        int c = tx + 32 * i;
        float s = 0.f, x, y;
        unpack2(acc[0][i], x, y); s += x + y;
        unpack2(acc[1][i], x, y); s += x + y;
        unpack2(acc[2][i], x, y); s += x;
        if (ty < 2) s += y;                 // ty==2 pair 8: y = pad row 17
        spart[ty * 96 + c] = s;
    }
}

// single-node GEMV, double-buffered weights (R13 pattern)
__device__ __forceinline__ ull gemv1(const ull* vec, const float* __restrict__ W,
                                     int ldw, int pi)
{
    ull a0 = 0ull;
    ull wp[8], wq[8];
#pragma unroll
    for (int u = 0; u < 8; u++) wp[u] = __ldg((const ull*)(W + u * ldw + 2 * pi));
#pragma unroll 1
    for (int k0 = 0; k0 < 96; k0 += 16) {
#pragma unroll
        for (int u = 0; u < 8; u++)
            wq[u] = __ldg((const ull*)(W + (k0 + 8 + u) * ldw + 2 * pi));
#pragma unroll
        for (int u = 0; u < 8; u++) fma2(a0, vec[k0 + u], wp[u]);
        if (k0 + 16 < 96) {
#pragma unroll
            for (int u = 0; u < 8; u++)
                wp[u] = __ldg((const ull*)(W + (k0 + 16 + u) * ldw + 2 * pi));
        }
#pragma unroll
        for (int u = 0; u < 8; u++) fma2(a0, vec[k0 + 8 + u], wq[u]);
    }
    return a0;
}

// ---------- fused per-step kernel: CTA = 1 node, 96 threads ----------
__global__ void __launch_bounds__(96, 7) step_kernel(
    int step,
    const int* __restrict__ edges, const int* __restrict__ target,
    const float* __restrict__ msg0_W, const float* __restrict__ msg0_b,
    const float* __restrict__ msg_Ws, const float* __restrict__ msg_bs,
    const float* __restrict__ W_ih, const float* __restrict__ W_hh,
    const float* __restrict__ pred_W, const float* __restrict__ pred_b,
    float* __restrict__ d_out)
{
    __shared__ __align__(16) float ZTa[96 * RS];
    __shared__ __align__(16) float ZTb[96 * RS];
    __shared__ __align__(16) ull   msgd[96];     // duplicated pairs [k]
    __shared__ __align__(16) ull   h2d[96];
    __shared__ float sQ[96];
    __shared__ float spart[288];
    __shared__ float gate_s[384];
    __shared__ float h2_s[96];
    __shared__ int   sedge[17];

    const int tid = threadIdx.x;
    const int tx = tid & 31, ty = tid >> 5;
    const int n = blockIdx.x;
    const int j = n & 63;

    const float* Pin  = g_P[step & 1];
    float*       Pout = g_P[(step + 1) & 1];

    if (tid < 17) sedge[tid] = (n & ~63) + __ldg(edges + j * 17 + tid);
    sQ[tid] = g_Q[n * 96 + tid];
    __syncthreads();

    // ---- Z0 = relu(P[edge] + Q): column tid ----
    {
        float q = sQ[tid];
        float* z = ZTa + tid * RS;
#pragma unroll
        for (int r = 0; r < 17; r++)
            z[r] = fmaxf(__ldg(Pin + sedge[r] * 96 + tid) + q, 0.f);
        z[17] = 0.f;
    }
    __syncthreads();

    // ---- 3 message layers ----
    layer_relu(ZTa, ZTb, msg_Ws,        msg_bs,      tx, ty); __syncthreads();
    layer_relu(ZTb, ZTa, msg_Ws + 9216, msg_bs + 96, tx, ty); __syncthreads();
    layer_sum (ZTa, spart, msg_Ws + 18432, tx, ty);           __syncthreads();

    {
        float m = spart[tid] + spart[96 + tid] + spart[192 + tid]
                + 17.f * __ldg(msg_bs + 192 + tid);
        msgd[tid] = pack2(m, m);
    }
    __syncthreads();

    // ---- gates: 192 pairs / 96 threads, 2 passes ----
#pragma unroll
    for (int pass = 0; pass < 2; pass++) {
        int pi = tid + 96 * pass;
        ull a = gemv1(msgd, W_ih, 384, pi);
        float x, y; unpack2(a, x, y);
        float2 xc = __ldg((const float2*)(g_Xc + n * 384 + 2 * pi));
        float2 gh = *(const float2*)(g_Ghh + n * 384 + 2 * pi);
        gate_s[2 * pi]     = x + xc.x + gh.x;
        gate_s[2 * pi + 1] = y + xc.y + gh.y;
    }
    __syncthreads();

    // ---- LSTM: dim = tid ----
    {
        float gi = gate_s[tid], gf = gate_s[96 + tid];
        float gg = gate_s[192 + tid], go = gate_s[288 + tid];
        float sp = g_s[n * 96 + tid];
        float s2 = sigf(gf) * sp + sigf(gi) * tanhf(gg);
        float h2 = sigf(go) * tanhf(s2);
        g_s[n * 96 + tid] = s2;
        h2_s[tid] = h2;
        h2d[tid] = pack2(h2, h2);
    }
    __syncthreads();

    // ---- next-step precompute ----
    if (step < NSTEP - 1) {
        {   // P (tid<48) / Q (tid>=48), pairs 0..47 each
            int isQ = (tid >= 48);
            int cp = tid - 48 * isQ;
            const float* Wp = msg0_W + (isQ ? 9216 : 0);
            ull a = gemv1(h2d, Wp, 96, cp);
            float x, y; unpack2(a, x, y);
            if (isQ) {
                x += __ldg(msg0_b + 2 * cp);
                y += __ldg(msg0_b + 2 * cp + 1);
                *(float2*)(g_Q + n * 96 + 2 * cp) = make_float2(x, y);
            } else {
                *(float2*)(Pout + n * 96 + 2 * cp) = make_float2(x, y);
            }
        }
#pragma unroll
        for (int pass = 0; pass < 2; pass++) {   // Ghh: 192 pairs, 2 passes
            int pi = tid + 96 * pass;
            ull a = gemv1(h2d, W_hh, 384, pi);
            float x, y; unpack2(a, x, y);
            *(float2*)(g_Ghh + n * 384 + 2 * pi) = make_float2(x, y);
        }
    }

    // ---- prediction head: warp 0, lanes 0..7 ----
    if (tid < 8) {
        float logit = __ldg(pred_b + tid);
#pragma unroll 8
        for (int k = 0; k < 96; k++)
            logit = fmaf(h2_s[k], __ldg(pred_W + k * 8 + tid), logit);
        const unsigned msk = 0xFFu;
        float mx = logit;
        for (int off = 4; off; off >>= 1) mx = fmaxf(mx, __shfl_xor_sync(msk, mx, off));
        float se = expf(logit - mx);
        for (int off = 4; off; off >>= 1) se += __shfl_xor_sync(msk, se, off);
        float lse = mx + logf(se);
        float bl = logit; int bc = tid;
        for (int off = 4; off; off >>= 1) {
            float ol = __shfl_xor_sync(msk, bl, off);
            int   oc = __shfl_xor_sync(msk, bc, off);
            if (ol > bl || (ol == bl && oc < bc)) { bl = ol; bc = oc; }
        }
        int tgt = __ldg(target + n) - 1;
        if (tid == tgt) g_nodeloss[step * 1024 + n] = lse - logit;
        if (tid == 0) {
            g_nodeok[step * 1024 + n] = (bc == tgt) ? 1 : 0;
            if (step == NSTEP - 1) d_out[33 + n] = (float)bc;
        }
    }
}

// ---------- prologue: CTA = node, 96 threads; ILP-batched ----------
__global__ void __launch_bounds__(96) prologue_kernel(
    const int* __restrict__ x,
    const float* __restrict__ digit_emb, const float* __restrict__ row_emb,
    const float* __restrict__ col_emb,
    const float* __restrict__ in0_W, const float* __restrict__ in0_b,
    const float* __restrict__ in_Ws, const float* __restrict__ in_bs,
    const float* __restrict__ W_ih, const float* __restrict__ b_ih,
    const float* __restrict__ b_hh, const float* __restrict__ msg0_b)
{
    __shared__ float feat[48], va[96], vb[96];
    const int tid = threadIdx.x;
    const int n = blockIdx.x;
    const int j = n & 63;

    if (tid < 16) {
        int xv = __ldg(x + n);
        feat[tid]      = __ldg(digit_emb + xv * 16 + tid);
        feat[16 + tid] = __ldg(row_emb + (j >> 3) * 16 + tid);
        feat[32 + tid] = __ldg(col_emb + (j & 7) * 16 + tid);
    }
    __syncthreads();

    {
        float a0 = __ldg(in0_b + tid), a1 = 0.f;
#pragma unroll 1
        for (int k0 = 0; k0 < 48; k0 += 8) {
            float wv[8];
#pragma unroll
            for (int u = 0; u < 8; u++) wv[u] = __ldg(in0_W + (k0 + u) * 96 + tid);
#pragma unroll
            for (int u = 0; u < 8; u += 2) {
                a0 = fmaf(feat[k0 + u],     wv[u],     a0);
                a1 = fmaf(feat[k0 + u + 1], wv[u + 1], a1);
            }
        }
        va[tid] = fmaxf(a0 + a1, 0.f);
    }
    __syncthreads();

#pragma unroll 1
    for (int l = 0; l < 3; l++) {
        const float* Wl = in_Ws + l * 9216;
        const float* src = (l == 1) ? vb : va;
        float*       dst = (l == 1) ? va : vb;
        float a0 = __ldg(in_bs + l * 96 + tid), a1 = 0.f;
#pragma unroll 1
        for (int k0 = 0; k0 < 96; k0 += 8) {
            float wv[8];
#pragma unroll
            for (int u = 0; u < 8; u++) wv[u] = __ldg(Wl + (k0 + u) * 96 + tid);
#pragma unroll
            for (int u = 0; u < 8; u += 2) {
                a0 = fmaf(src[k0 + u],     wv[u],     a0);
                a1 = fmaf(src[k0 + u + 1], wv[u + 1], a1);
            }
        }
        float acc = a0 + a1;
        dst[tid] = (l < 2) ? fmaxf(acc, 0.f) : acc;
        __syncthreads();
    }
    // xin in vb

#pragma unroll
    for (int pass = 0; pass < 2; pass++) {
        int pi = tid + 96 * pass;
        ull acc = 0ull;
#pragma unroll 1
        for (int k0 = 0; k0 < 96; k0 += 8) {
            ull wp[8];
#pragma unroll
            for (int u = 0; u < 8; u++)
                wp[u] = __ldg((const ull*)(W_ih + (96 + k0 + u) * 384 + 2 * pi));
#pragma unroll
            for (int u = 0; u < 8; u++) {
                float xk = vb[k0 + u];
                fma2(acc, pack2(xk, xk), wp[u]);
            }
        }
        float xx, yy; unpack2(acc, xx, yy);
        g_Xc[n * 384 + 2 * pi]     = xx + __ldg(b_ih + 2 * pi)     + __ldg(b_hh + 2 * pi);
        g_Xc[n * 384 + 2 * pi + 1] = yy + __ldg(b_ih + 2 * pi + 1) + __ldg(b_hh + 2 * pi + 1);
    }

    g_P[0][n * 96 + tid] = 0.f;
    g_Q[n * 96 + tid]    = __ldg(msg0_b + tid);
    g_Ghh[n * 384 + tid]       = 0.f;
    g_Ghh[n * 384 + 96 + tid]  = 0.f;
    g_Ghh[n * 384 + 192 + tid] = 0.f;
    g_Ghh[n * 384 + 288 + tid] = 0.f;
    g_s[n * 96 + tid] = 0.f;
}

// ---------- epilogue ----------
__global__ void __launch_bounds__(512) epilogue_kernel(float* __restrict__ d_out)
{
    __shared__ int   cnt[32];
    __shared__ float red[512];
    int tid = threadIdx.x;
    if (tid < 32) cnt[tid] = 0;
    __syncthreads();

    int s = tid >> 4, b = tid & 15;
    int ok = 1;
    for (int jj = 0; jj < 64; jj++) ok &= g_nodeok[s * 1024 + b * 64 + jj];
    atomicAdd(&cnt[s], ok);

    float ls = 0.f;
    for (int i = tid; i < NSTEP * 1024; i += 512) ls += g_nodeloss[i];
    red[tid] = ls;
    __syncthreads();
    for (int off = 256; off; off >>= 1) {
        if (tid < off) red[tid] += red[tid + off];
        __syncthreads();
    }
    if (tid == 0)  d_out[0] = red[0] / (1024.f * 32.f);
    if (tid < 32)  d_out[1 + tid] = cnt[tid] * (1.f / 16.f);
}

// ---------- launch ----------
extern "C" void kernel_launch(void* const* d_in, const int* in_sizes, int n_in,
                              void* d_out, int out_size)
{
    (void)in_sizes; (void)n_in; (void)out_size;
    const int*   x         = (const int*)  d_in[0];
    const int*   target    = (const int*)  d_in[1];
    const int*   edges     = (const int*)  d_in[2];
    const float* digit_emb = (const float*)d_in[3];
    const float* row_emb   = (const float*)d_in[4];
    const float* col_emb   = (const float*)d_in[5];
    const float* in0_W     = (const float*)d_in[6];
    const float* in0_b     = (const float*)d_in[7];
    const float* in_Ws     = (const float*)d_in[8];
    const float* in_bs     = (const float*)d_in[9];
    const float* msg0_W    = (const float*)d_in[10];
    const float* msg0_b    = (const float*)d_in[11];
    const float* msg_Ws    = (const float*)d_in[12];
    const float* msg_bs    = (const float*)d_in[13];
    const float* W_ih      = (const float*)d_in[14];
    const float* W_hh      = (const float*)d_in[15];
    const float* b_ih      = (const float*)d_in[16];
    const float* b_hh      = (const float*)d_in[17];
    const float* pred_W    = (const float*)d_in[18];
    const float* pred_b    = (const float*)d_in[19];
    float* out = (float*)d_out;

    prologue_kernel<<<1024, 96>>>(x, digit_emb, row_emb, col_emb,
                                  in0_W, in0_b, in_Ws, in_bs,
                                  W_ih, b_ih, b_hh, msg0_b);
    for (int s = 0; s < NSTEP; s++)
        step_kernel<<<1024, 96>>>(s, edges, target,
                                  msg0_W, msg0_b, msg_Ws, msg_bs,
                                  W_ih, W_hh, pred_W, pred_b, out);
    epilogue_kernel<<<1, 512>>>(out);
}

// round 17
// speedup vs baseline: 1.1220x; 1.1220x over previous
#include <cuda_runtime.h>
#include <math.h>

// RRN sudoku. B=16, N=64, DEG=17, H=96, 32 steps.
// Round 17: R13 + split-K warps. CTA = 2 nodes x 192 threads (grid 512):
// warps 0-2 do k[0,48), warps 3-5 do k[48,96) of the same tile; in-place
// partial combine; single-pass tails. Same instr count, 1.8x warps/SM.

#define NSTEP 32
#define RS 44
typedef unsigned long long ull;

// ---------- device scratch (allocation-free) ----------
__device__ float g_P[2][1024 * 96];
__device__ float g_Q[1024 * 96];
__device__ float g_Ghh[1024 * 384];
__device__ float g_Xc[1024 * 384];
__device__ float g_s[1024 * 96];
__device__ float g_nodeloss[NSTEP * 1024];
__device__ int   g_nodeok[NSTEP * 1024];

// ---------- packed f32x2 helpers ----------
__device__ __forceinline__ ull pack2(float x, float y) {
    ull r; asm("mov.b64 %0,{%1,%2};" : "=l"(r) : "f"(x), "f"(y)); return r;
}
__device__ __forceinline__ void unpack2(ull v, float& x, float& y) {
    asm("mov.b64 {%0,%1},%2;" : "=f"(x), "=f"(y) : "l"(v));
}
__device__ __forceinline__ void fma2(ull& d, ull a, ull b) {
    asm("fma.rn.f32x2 %0,%1,%2,%0;" : "+l"(d) : "l"(a), "l"(b));
}
__device__ __forceinline__ float sigf(float x) { return 1.f / (1.f + expf(-x)); }

__device__ __forceinline__ void ldw4(float w[4][3], const float* __restrict__ Wg,
                                     int k, int tx)
{
#pragma unroll
    for (int u = 0; u < 4; u++)
#pragma unroll
        for (int i = 0; i < 3; i++)
            w[u][i] = __ldg(Wg + (k + u) * 96 + tx + 32 * i);
}

__device__ __forceinline__ void blk4(const float* Zk, int k, int rb,
                                     const float w[4][3], ull acc[6][3])
{
#pragma unroll
    for (int u = 0; u < 4; u++) {
        const float* zrow = Zk + (k + u) * RS + rb;
        ulonglong2 zA = *(const ulonglong2*)(zrow);
        ulonglong2 zB = *(const ulonglong2*)(zrow + 4);
        ulonglong2 zC = *(const ulonglong2*)(zrow + 8);
#pragma unroll
        for (int i = 0; i < 3; i++) {
            ull w2 = pack2(w[u][i], w[u][i]);
            fma2(acc[0][i], zA.x, w2); fma2(acc[1][i], zA.y, w2);
            fma2(acc[2][i], zB.x, w2); fma2(acc[3][i], zB.y, w2);
            fma2(acc[4][i], zC.x, w2); fma2(acc[5][i], zC.y, w2);
        }
    }
}

// half-K loop: 48 k values starting at Zk / Wk (pre-offset by caller)
__device__ __forceinline__ void kloop48(const float* Zk, const float* __restrict__ Wk,
                                        int tx, int rb, ull acc[6][3])
{
#pragma unroll
    for (int j = 0; j < 6; j++)
#pragma unroll
        for (int i = 0; i < 3; i++) acc[j][i] = 0ull;

    float wA[4][3], wB[4][3];
    ldw4(wA, Wk, 0, tx);
#pragma unroll 1
    for (int k0 = 0; k0 < 48; k0 += 8) {
        ldw4(wB, Wk, k0 + 4, tx);
        blk4(Zk, k0, rb, wA, acc);
        if (k0 + 8 < 48) ldw4(wA, Wk, k0 + 8, tx);
        blk4(Zk, k0 + 4, rb, wB, acc);
    }
}

// ---------- relu layer, split-K with in-place combine ----------
__device__ __forceinline__ void layer_relu(const float* Zin, float* Zout,
                                           const float* __restrict__ Wg,
                                           const float* __restrict__ bias,
                                           int tx, int ty, int tz)
{
    ull acc[6][3];
    kloop48(Zin + tz * 48 * RS, Wg + tz * 48 * 96, tx, 12 * ty, acc);

    if (tz == 1) {                                   // store raw partials
#pragma unroll
        for (int i = 0; i < 3; i++) {
            int c = tx + 32 * i;
#pragma unroll
            for (int j = 0; j < 6; j++)
                *(ull*)(Zout + c * RS + 2 * (6 * ty + j)) = acc[j][i];
        }
    }
    __syncthreads();
    if (tz == 0) {                                   // combine + bias + relu
#pragma unroll
        for (int i = 0; i < 3; i++) {
            int c = tx + 32 * i;
            float bv = __ldg(bias + c);
#pragma unroll
            for (int j = 0; j < 6; j++) {
                ull part = *(ull*)(Zout + c * RS + 2 * (6 * ty + j));
                float px, py, x, y;
                unpack2(part, px, py);
                unpack2(acc[j][i], x, y);
                x = fmaxf(x + px + bv, 0.f);
                y = fmaxf(y + py + bv, 0.f);
                *(ull*)(Zout + c * RS + 2 * (6 * ty + j)) = pack2(x, y);
            }
        }
    }
    __syncthreads();
}

// last layer: partial per-node row sums -> spart[tz*576 + ty*192 + nd*96 + c]
__device__ __forceinline__ void layer_sum(const float* Zin, float* spart,
                                          const float* __restrict__ Wg,
                                          int tx, int ty, int tz)
{
    ull acc[6][3];
    kloop48(Zin + tz * 48 * RS, Wg + tz * 48 * 96, tx, 12 * ty, acc);
    // pairs owned: p = 6ty+j. node0 = p 0..8 (p8 drop y = pad row17),
    // node1 = p 9..17 (p17 drop y = pad row35).
#pragma unroll
    for (int i = 0; i < 3; i++) {
        int c = tx + 32 * i;
        float s0 = 0.f, s1 = 0.f;
        float x, y;
        if (ty == 0) {
#pragma unroll
            for (int j = 0; j < 6; j++) { unpack2(acc[j][i], x, y); s0 += x + y; }
        } else if (ty == 1) {
            unpack2(acc[0][i], x, y); s0 += x + y;
            unpack2(acc[1][i], x, y); s0 += x + y;
            unpack2(acc[2][i], x, y); s0 += x;        // p8 (y = pad row17)
            unpack2(acc[3][i], x, y); s1 += x + y;
            unpack2(acc[4][i], x, y); s1 += x + y;
            unpack2(acc[5][i], x, y); s1 += x + y;
        } else {
#pragma unroll
            for (int j = 0; j < 5; j++) { unpack2(acc[j][i], x, y); s1 += x + y; }
            unpack2(acc[5][i], x, y); s1 += x;        // p17 (y = pad row35)
        }
        spart[tz * 576 + ty * 192 + c]      = s0;
        spart[tz * 576 + ty * 192 + 96 + c] = s1;
    }
}

// dual-node GEMV over duplicated-pair smem vector, double-buffered weights
__device__ __forceinline__ void gemv2(const ull* vec, const float* __restrict__ W,
                                      int ldw, int pi, ull& a0, ull& a1)
{
    a0 = 0ull; a1 = 0ull;
    ull wp[8], wq[8];
#pragma unroll
    for (int u = 0; u < 8; u++) wp[u] = __ldg((const ull*)(W + u * ldw + 2 * pi));
#pragma unroll 1
    for (int k0 = 0; k0 < 96; k0 += 16) {
#pragma unroll
        for (int u = 0; u < 8; u++)
            wq[u] = __ldg((const ull*)(W + (k0 + 8 + u) * ldw + 2 * pi));
#pragma unroll
        for (int u = 0; u < 8; u++) {
            ulonglong2 m = *(const ulonglong2*)(vec + 2 * (k0 + u));
            fma2(a0, m.x, wp[u]);
            fma2(a1, m.y, wp[u]);
        }
        if (k0 + 16 < 96) {
#pragma unroll
            for (int u = 0; u < 8; u++)
                wp[u] = __ldg((const ull*)(W + (k0 + 16 + u) * ldw + 2 * pi));
        }
#pragma unroll
        for (int u = 0; u < 8; u++) {
            ulonglong2 m = *(const ulonglong2*)(vec + 2 * (k0 + 8 + u));
            fma2(a0, m.x, wq[u]);
            fma2(a1, m.y, wq[u]);
        }
    }
}

// ---------- fused per-step kernel: CTA = 2 nodes, 192 threads ----------
__global__ void __launch_bounds__(192, 3) step_kernel(
    int step,
    const int* __restrict__ edges, const int* __restrict__ target,
    const float* __restrict__ msg0_W, const float* __restrict__ msg0_b,
    const float* __restrict__ msg_Ws, const float* __restrict__ msg_bs,
    const float* __restrict__ W_ih, const float* __restrict__ W_hh,
    const float* __restrict__ pred_W, const float* __restrict__ pred_b,
    float* __restrict__ d_out)
{
    __shared__ __align__(16) float ZTa[96 * RS];
    __shared__ __align__(16) float ZTb[96 * RS];
    __shared__ __align__(16) ull   msgd[192];    // [k*2 + nd], duplicated pairs
    __shared__ __align__(16) ull   h2d[192];
    __shared__ float sQ[192];
    __shared__ float spart[1152];
    __shared__ float gate_s[768];
    __shared__ float h2_s[192];
    __shared__ int   sedge[34];

    const int tid = threadIdx.x;
    const int tx = tid & 31;
    const int w  = tid >> 5;
    const int ty = (w < 3) ? w : (w - 3);        // row-pair group 0..2
    const int tz = (w < 3) ? 0 : 1;              // k-half
    const int n0 = blockIdx.x * 2;

    const float* Pin  = g_P[step & 1];
    float*       Pout = g_P[(step + 1) & 1];

    if (tid < 34) {
        int nd = (tid >= 17), r = tid - 17 * nd;
        int j = (n0 + nd) & 63;
        sedge[tid] = (n0 & ~63) + __ldg(edges + j * 17 + r);
    }
    sQ[tid] = g_Q[n0 * 96 + tid];
    __syncthreads();

    // ---- Z0 = relu(P[edge] + Q); 192 threads: c = tid%96, h = tid/96 ----
    {
        int c = tid % 96, h = tid / 96;
        float q0 = sQ[c], q1 = sQ[96 + c];
        float* z = ZTa + c * RS;
        for (int r = h; r < 17; r += 2)
            z[r] = fmaxf(__ldg(Pin + sedge[r] * 96 + c) + q0, 0.f);
        for (int r = h; r < 17; r += 2)
            z[18 + r] = fmaxf(__ldg(Pin + sedge[17 + r] * 96 + c) + q1, 0.f);
        if (h == 1) { z[17] = 0.f; z[35] = 0.f; }
    }
    __syncthreads();

    // ---- 3 message layers (split-K) ----
    layer_relu(ZTa, ZTb, msg_Ws,        msg_bs,      tx, ty, tz);
    layer_relu(ZTb, ZTa, msg_Ws + 9216, msg_bs + 96, tx, ty, tz);
    layer_sum (ZTa, spart, msg_Ws + 18432, tx, ty, tz);
    __syncthreads();

    if (tid < 96) {
        float bv = 17.f * __ldg(msg_bs + 192 + tid);
        float m0 = spart[tid]      + spart[192 + tid] + spart[384 + tid]
                 + spart[576 + tid] + spart[768 + tid] + spart[960 + tid] + bv;
        float m1 = spart[96 + tid] + spart[288 + tid] + spart[480 + tid]
                 + spart[672 + tid] + spart[864 + tid] + spart[1056 + tid] + bv;
        msgd[tid * 2]     = pack2(m0, m0);
        msgd[tid * 2 + 1] = pack2(m1, m1);
    }
    __syncthreads();

    // ---- gates: 192 pairs, one per thread ----
    {
        int pi = tid;
        ull a0, a1;
        gemv2(msgd, W_ih, 384, pi, a0, a1);
        float x0, y0, x1, y1; unpack2(a0, x0, y0); unpack2(a1, x1, y1);
        float2 xc0 = *(const float2*)(g_Xc  + n0 * 384 + 2 * pi);
        float2 gh0 = *(const float2*)(g_Ghh + n0 * 384 + 2 * pi);
        float2 xc1 = *(const float2*)(g_Xc  + (n0 + 1) * 384 + 2 * pi);
        float2 gh1 = *(const float2*)(g_Ghh + (n0 + 1) * 384 + 2 * pi);
        gate_s[2 * pi]           = x0 + xc0.x + gh0.x;
        gate_s[2 * pi + 1]       = y0 + xc0.y + gh0.y;
        gate_s[384 + 2 * pi]     = x1 + xc1.x + gh1.x;
        gate_s[384 + 2 * pi + 1] = y1 + xc1.y + gh1.y;
    }
    __syncthreads();

    // ---- LSTM: 192 threads = 2 nodes x 96 dims ----
    {
        int nd = tid / 96, dim = tid % 96;
        int n = n0 + nd;
        float gi = gate_s[nd * 384 + dim];
        float gf = gate_s[nd * 384 + 96 + dim];
        float gg = gate_s[nd * 384 + 192 + dim];
        float go = gate_s[nd * 384 + 288 + dim];
        float sp = g_s[n * 96 + dim];
        float s2 = sigf(gf) * sp + sigf(gi) * tanhf(gg);
        float h2 = sigf(go) * tanhf(s2);
        g_s[n * 96 + dim] = s2;
        h2_s[nd * 96 + dim] = h2;
        h2d[dim * 2 + nd] = pack2(h2, h2);
    }
    __syncthreads();

    // ---- next-step precompute ----
    if (step < NSTEP - 1) {
        {   // Ghh: 192 pairs, one per thread
            int pi = tid;
            ull a0, a1;
            gemv2(h2d, W_hh, 384, pi, a0, a1);
            float x0, y0, x1, y1; unpack2(a0, x0, y0); unpack2(a1, x1, y1);
            *(float2*)(g_Ghh + n0 * 384 + 2 * pi)       = make_float2(x0, y0);
            *(float2*)(g_Ghh + (n0 + 1) * 384 + 2 * pi) = make_float2(x1, y1);
        }
        if (tid < 96) {   // P (tid<48) / Q (48<=tid<96)
            int isQ = (tid >= 48);
            int cp = tid - 48 * isQ;
            const float* Wp = msg0_W + (isQ ? 9216 : 0);
            ull a0, a1;
            gemv2(h2d, Wp, 96, cp, a0, a1);
            float x0, y0, x1, y1; unpack2(a0, x0, y0); unpack2(a1, x1, y1);
            if (isQ) {
                float bx = __ldg(msg0_b + 2 * cp), by = __ldg(msg0_b + 2 * cp + 1);
                *(float2*)(g_Q + n0 * 96 + 2 * cp)       = make_float2(x0 + bx, y0 + by);
                *(float2*)(g_Q + (n0 + 1) * 96 + 2 * cp) = make_float2(x1 + bx, y1 + by);
            } else {
                *(float2*)(Pout + n0 * 96 + 2 * cp)       = make_float2(x0, y0);
                *(float2*)(Pout + (n0 + 1) * 96 + 2 * cp) = make_float2(x1, y1);
            }
        }
    }

    // ---- prediction head: warp 0 -> node0, warp 3 -> node1 (lanes 0..7) ----
    if ((w == 0 || w == 3) && tx < 8) {
        int nd = (w == 3) ? 1 : 0;
        int n = n0 + nd, d = tx;
        float logit = __ldg(pred_b + d);
        const float* hr = h2_s + nd * 96;
#pragma unroll 8
        for (int k = 0; k < 96; k++)
            logit = fmaf(hr[k], __ldg(pred_W + k * 8 + d), logit);
        const unsigned msk = 0xFFu;
        float mx = logit;
        for (int off = 4; off; off >>= 1) mx = fmaxf(mx, __shfl_xor_sync(msk, mx, off));
        float se = expf(logit - mx);
        for (int off = 4; off; off >>= 1) se += __shfl_xor_sync(msk, se, off);
        float lse = mx + logf(se);
        float bl = logit; int bc = d;
        for (int off = 4; off; off >>= 1) {
            float ol = __shfl_xor_sync(msk, bl, off);
            int   oc = __shfl_xor_sync(msk, bc, off);
            if (ol > bl || (ol == bl && oc < bc)) { bl = ol; bc = oc; }
        }
        int tgt = __ldg(target + n) - 1;
        if (d == tgt) g_nodeloss[step * 1024 + n] = lse - logit;
        if (d == 0) {
            g_nodeok[step * 1024 + n] = (bc == tgt) ? 1 : 0;
            if (step == NSTEP - 1) d_out[33 + n] = (float)bc;
        }
    }
}

// ---------- prologue: CTA = node, 96 threads; ILP-batched ----------
__global__ void __launch_bounds__(96) prologue_kernel(
    const int* __restrict__ x,
    const float* __restrict__ digit_emb, const float* __restrict__ row_emb,
    const float* __restrict__ col_emb,
    const float* __restrict__ in0_W, const float* __restrict__ in0_b,
    const float* __restrict__ in_Ws, const float* __restrict__ in_bs,
    const float* __restrict__ W_ih, const float* __restrict__ b_ih,
    const float* __restrict__ b_hh, const float* __restrict__ msg0_b)
{
    __shared__ float feat[48], va[96], vb[96];
    const int tid = threadIdx.x;
    const int n = blockIdx.x;
    const int j = n & 63;

    if (tid < 16) {
        int xv = __ldg(x + n);
        feat[tid]      = __ldg(digit_emb + xv * 16 + tid);
        feat[16 + tid] = __ldg(row_emb + (j >> 3) * 16 + tid);
        feat[32 + tid] = __ldg(col_emb + (j & 7) * 16 + tid);
    }
    __syncthreads();

    {
        float a0 = __ldg(in0_b + tid), a1 = 0.f;
#pragma unroll 1
        for (int k0 = 0; k0 < 48; k0 += 8) {
            float wv[8];
#pragma unroll
            for (int u = 0; u < 8; u++) wv[u] = __ldg(in0_W + (k0 + u) * 96 + tid);
#pragma unroll
            for (int u = 0; u < 8; u += 2) {
                a0 = fmaf(feat[k0 + u],     wv[u],     a0);
                a1 = fmaf(feat[k0 + u + 1], wv[u + 1], a1);
            }
        }
        va[tid] = fmaxf(a0 + a1, 0.f);
    }
    __syncthreads();

#pragma unroll 1
    for (int l = 0; l < 3; l++) {
        const float* Wl = in_Ws + l * 9216;
        const float* src = (l == 1) ? vb : va;
        float*       dst = (l == 1) ? va : vb;
        float a0 = __ldg(in_bs + l * 96 + tid), a1 = 0.f;
#pragma unroll 1
        for (int k0 = 0; k0 < 96; k0 += 8) {
            float wv[8];
#pragma unroll
            for (int u = 0; u < 8; u++) wv[u] = __ldg(Wl + (k0 + u) * 96 + tid);
#pragma unroll
            for (int u = 0; u < 8; u += 2) {
                a0 = fmaf(src[k0 + u],     wv[u],     a0);
                a1 = fmaf(src[k0 + u + 1], wv[u + 1], a1);
            }
        }
        float acc = a0 + a1;
        dst[tid] = (l < 2) ? fmaxf(acc, 0.f) : acc;
        __syncthreads();
    }
    // xin in vb

#pragma unroll
    for (int pass = 0; pass < 2; pass++) {
        int pi = tid + 96 * pass;
        ull acc = 0ull;
#pragma unroll 1
        for (int k0 = 0; k0 < 96; k0 += 8) {
            ull wp[8];
#pragma unroll
            for (int u = 0; u < 8; u++)
                wp[u] = __ldg((const ull*)(W_ih + (96 + k0 + u) * 384 + 2 * pi));
#pragma unroll
            for (int u = 0; u < 8; u++) {
                float xk = vb[k0 + u];
                fma2(acc, pack2(xk, xk), wp[u]);
            }
        }
        float xx, yy; unpack2(acc, xx, yy);
        g_Xc[n * 384 + 2 * pi]     = xx + __ldg(b_ih + 2 * pi)     + __ldg(b_hh + 2 * pi);
        g_Xc[n * 384 + 2 * pi + 1] = yy + __ldg(b_ih + 2 * pi + 1) + __ldg(b_hh + 2 * pi + 1);
    }

    g_P[0][n * 96 + tid] = 0.f;
    g_Q[n * 96 + tid]    = __ldg(msg0_b + tid);
    g_Ghh[n * 384 + tid]       = 0.f;
    g_Ghh[n * 384 + 96 + tid]  = 0.f;
    g_Ghh[n * 384 + 192 + tid] = 0.f;
    g_Ghh[n * 384 + 288 + tid] = 0.f;
    g_s[n * 96 + tid] = 0.f;
}

// ---------- epilogue ----------
__global__ void __launch_bounds__(512) epilogue_kernel(float* __restrict__ d_out)
{
    __shared__ int   cnt[32];
    __shared__ float red[512];
    int tid = threadIdx.x;
    if (tid < 32) cnt[tid] = 0;
    __syncthreads();

    int s = tid >> 4, b = tid & 15;
    int ok = 1;
    for (int jj = 0; jj < 64; jj++) ok &= g_nodeok[s * 1024 + b * 64 + jj];
    atomicAdd(&cnt[s], ok);

    float ls = 0.f;
    for (int i = tid; i < NSTEP * 1024; i += 512) ls += g_nodeloss[i];
    red[tid] = ls;
    __syncthreads();
    for (int off = 256; off; off >>= 1) {
        if (tid < off) red[tid] += red[tid + off];
        __syncthreads();
    }
    if (tid == 0)  d_out[0] = red[0] / (1024.f * 32.f);
    if (tid < 32)  d_out[1 + tid] = cnt[tid] * (1.f / 16.f);
}

// ---------- launch ----------
extern "C" void kernel_launch(void* const* d_in, const int* in_sizes, int n_in,
                              void* d_out, int out_size)
{
    (void)in_sizes; (void)n_in; (void)out_size;
    const int*   x         = (const int*)  d_in[0];
    const int*   target    = (const int*)  d_in[1];
    const int*   edges     = (const int*)  d_in[2];
    const float* digit_emb = (const float*)d_in[3];
    const float* row_emb   = (const float*)d_in[4];
    const float* col_emb   = (const float*)d_in[5];
    const float* in0_W     = (const float*)d_in[6];
    const float* in0_b     = (const float*)d_in[7];
    const float* in_Ws     = (const float*)d_in[8];
    const float* in_bs     = (const float*)d_in[9];
    const float* msg0_W    = (const float*)d_in[10];
    const float* msg0_b    = (const float*)d_in[11];
    const float* msg_Ws    = (const float*)d_in[12];
    const float* msg_bs    = (const float*)d_in[13];
    const float* W_ih      = (const float*)d_in[14];
    const float* W_hh      = (const float*)d_in[15];
    const float* b_ih      = (const float*)d_in[16];
    const float* b_hh      = (const float*)d_in[17];
    const float* pred_W    = (const float*)d_in[18];
    const float* pred_b    = (const float*)d_in[19];
    float* out = (float*)d_out;

    prologue_kernel<<<1024, 96>>>(x, digit_emb, row_emb, col_emb,
                                  in0_W, in0_b, in_Ws, in_bs,
                                  W_ih, b_ih, b_hh, msg0_b);
    for (int s = 0; s < NSTEP; s++)
        step_kernel<<<512, 192>>>(s, edges, target,
                                  msg0_W, msg0_b, msg_Ws, msg_bs,
                                  W_ih, W_hh, pred_W, pred_b, out);
    epilogue_kernel<<<1, 512>>>(out);
}